// round 15
// baseline (speedup 1.0000x reference)
#include <cuda_runtime.h>

#define BB 8
#define LL 512
#define DD 128
#define INV_SCALE 0.08838834764831843f   // 1/sqrt(128)

typedef unsigned long long ull;

// ---- scratch (no cudaMalloc allowed) ----
__device__ float g_EQ[BB*LL*DD];   // exp(2*Qproj)
__device__ float g_EK[BB*LL*DD];   // exp(2*Kproj)
__device__ float g_V [BB*LL*DD];

__device__ __forceinline__ float frcp(float x) {
    float y;
    asm("rcp.approx.f32 %0, %1;" : "=f"(y) : "f"(x));
    return y;
}
__device__ __forceinline__ ull ffma2(ull a, ull b, ull c) {
    ull d;
    asm("fma.rn.f32x2 %0, %1, %2, %3;" : "=l"(d) : "l"(a), "l"(b), "l"(c));
    return d;
}
__device__ __forceinline__ ull fmul2(ull a, ull b) {
    ull d;
    asm("mul.rn.f32x2 %0, %1, %2;" : "=l"(d) : "l"(a), "l"(b));
    return d;
}
__device__ __forceinline__ ull fadd2(ull a, ull b) {
    ull d;
    asm("add.rn.f32x2 %0, %1, %2;" : "=l"(d) : "l"(a), "l"(b));
    return d;
}
__device__ __forceinline__ ull pack2(float x) {
    ull d;
    asm("mov.b64 %0, {%1, %1};" : "=l"(d) : "f"(x));
    return d;
}
__device__ __forceinline__ ull pack2two(float x, float y) {
    ull d;
    asm("mov.b64 %0, {%1, %2};" : "=l"(d) : "f"(x), "f"(y));
    return d;
}
__device__ __forceinline__ float2 unpack2(ull v) {
    float2 r;
    asm("mov.b64 {%0, %1}, %2;" : "=f"(r.x), "=f"(r.y) : "l"(v));
    return r;
}

// =====================================================================
// Projection (96 blocks, 128x128 tiles, 256 thr, 8x8 tile, FFMA2).
// Epilogue: exp(2x) for Q,K; identity for V.  (measured ~23 us)
// =====================================================================
#define XS_PITCH 129
#define WT_PITCH 130
#define PROJ_SMEM_FLOATS (128*XS_PITCH + 128*WT_PITCH)

__global__ void __launch_bounds__(256) proj_kernel(
    const float* __restrict__ Xq, const float* __restrict__ Xk, const float* __restrict__ Xv,
    const float* __restrict__ Wq, const float* __restrict__ bq,
    const float* __restrict__ Wk, const float* __restrict__ bk,
    const float* __restrict__ Wv, const float* __restrict__ bv)
{
    extern __shared__ float sm[];
    float* Xs = sm;                    // [128][129]
    float* Wt = sm + 128*XS_PITCH;     // [128][130]  Wt[d][c]
    __shared__ float bs[DD];

    int bx  = blockIdx.x;
    int mat = bx >> 5;
    int rt  = bx & 31;
    const float *X, *W, *bias;
    float* out;
    if (mat == 0)      { X = Xq; W = Wq; bias = bq; out = g_EQ; }
    else if (mat == 1) { X = Xk; W = Wk; bias = bk; out = g_EK; }
    else               { X = Xv; W = Wv; bias = bv; out = g_V;  }

    int tid = threadIdx.x;
    const float4* Xg = (const float4*)(X + rt*128*DD);
    const float4* Wg = (const float4*)W;
    #pragma unroll
    for (int it = 0; it < 16; ++it) {
        int idx = it*256 + tid;           // 0..4095
        {
            int d4  = idx & 31;
            int r   = idx >> 5;
            float4 xv = Xg[idx];
            float* xd = Xs + r*XS_PITCH + 4*d4;
            xd[0] = xv.x; xd[1] = xv.y; xd[2] = xv.z; xd[3] = xv.w;
        }
        {
            int rlo = idx & 31;
            int hi  = idx >> 5;
            int d4  = hi & 31;
            int r   = ((hi >> 5) << 5) + rlo;
            float4 wv = Wg[r*32 + d4];
            Wt[(4*d4+0)*WT_PITCH + r] = wv.x;
            Wt[(4*d4+1)*WT_PITCH + r] = wv.y;
            Wt[(4*d4+2)*WT_PITCH + r] = wv.z;
            Wt[(4*d4+3)*WT_PITCH + r] = wv.w;
        }
    }
    if (tid < DD) bs[tid] = bias[tid];
    __syncthreads();

    int tr = tid >> 4;
    int tc = tid & 15;
    const float* xb = Xs + (tr*8)*XS_PITCH;
    const float* wb = Wt + tc*8;

    ull acc[8][4];
    #pragma unroll
    for (int i = 0; i < 8; ++i)
        #pragma unroll
        for (int j = 0; j < 4; ++j) acc[i][j] = 0ull;

    #pragma unroll 4
    for (int d = 0; d < DD; ++d) {
        float xs[8]; ull xp[8]; ull wp[4];
        #pragma unroll
        for (int i = 0; i < 8; ++i) xs[i] = xb[i*XS_PITCH + d];
        #pragma unroll
        for (int j = 0; j < 4; ++j) wp[j] = *(const ull*)(wb + d*WT_PITCH + 2*j);
        #pragma unroll
        for (int i = 0; i < 8; ++i) xp[i] = pack2(xs[i]);
        #pragma unroll
        for (int i = 0; i < 8; ++i)
            #pragma unroll
            for (int j = 0; j < 4; ++j) acc[i][j] = ffma2(xp[i], wp[j], acc[i][j]);
    }

    int rbase = rt*128 + tr*8;
    #pragma unroll
    for (int i = 0; i < 8; ++i) {
        float* orow = out + (rbase + i)*DD + tc*8;
        #pragma unroll
        for (int j = 0; j < 4; ++j) {
            float2 v = unpack2(acc[i][j]);
            float o0 = v.x + bs[tc*8 + 2*j+0];
            float o1 = v.y + bs[tc*8 + 2*j+1];
            if (mat != 2) { o0 = __expf(2.0f*o0); o1 = __expf(2.0f*o1); }
            orow[2*j+0] = o0;
            orow[2*j+1] = o1;
        }
    }
}

// =====================================================================
// Attention. Block = (batch b, 16-q tile), 512 threads (16 warps),
// grid 256 -> covers all 148 SMs, 2 CTAs/SM co-resident (smem ~74KB)
// so barrier walls of one CTA overlap compute of the other.
// Phase 1 (R13 algebra): iw = 1/(-2w); Eq'' = Eq*iw.
//   D = ffma2(dupEq'', ekpair, dupiw); score(shifted) = sum_d 1/D:
//   per d-quad: N=(D0+D1)*P23+(D2+D3)*P01, acc += N*rcp(P01*P23)
//   8 tiles of 64 k; warp owns k-pairs (2w, 2w+1);
//   lane = (q = lane&15, kk = lane>>4) -> ONE chain per lane.
// Phase 2: warp w softmaxes row w (w < 16).
// Phase 3: O = P @ V, FFMA2; warp = (row-pair w&7, d-half w>>3).
// smem (floats):
//   S[16][516]         @ 0      8256  (first 128 reused as iw temp)
//   EKa[32][33] ull2   @ 8256   4224  (pairs d0,d1; Vp reuses EKa+EKb)
//   EKb[32][33] ull2   @ 12480  4224  (pairs d2,d3)
//   EQ4[32][16] float4 @ 16704  2048  (EQ4[d4][q] = Eq'' quad)
//   IWa[32] ull2       @ 18752   128
//   IWb[32] ull2       @ 18880   128
//   rinv[16]           @ 19008    16
// =====================================================================
#define S_PITCH 516
#define SM_S    0
#define SM_EKA  8256
#define SM_EKB  12480
#define SM_EQ4  16704
#define SM_IWA  18752
#define SM_IWB  18880
#define SM_RINV 19008
#define ATTN_SMEM_FLOATS 19024    // 76096 B

__global__ void __launch_bounds__(512, 2) attn_kernel(
    const float* __restrict__ wdel, const float* __restrict__ wsig,
    const float* __restrict__ wthe, float* __restrict__ out)
{
    extern __shared__ float sm[];
    float*      S    = sm + SM_S;
    ulonglong2* EKa  = (ulonglong2*)(sm + SM_EKA);   // [32][33]
    ulonglong2* EKb  = (ulonglong2*)(sm + SM_EKB);   // [32][33]
    float4*     EQ4  = (float4*)(sm + SM_EQ4);       // [d4][q] (16 q)
    ulonglong2* IWa  = (ulonglong2*)(sm + SM_IWA);
    ulonglong2* IWb  = (ulonglong2*)(sm + SM_IWB);
    float*      rinv = sm + SM_RINV;
    float*      iw   = sm + SM_S;                    // temp during init

    int tid  = threadIdx.x;
    int w    = tid >> 5;
    int lane = tid & 31;
    int b    = blockIdx.x >> 5;
    int qt   = blockIdx.x & 31;
    int qbase = qt * 16;

    const float* EQg = g_EQ + (b*LL + qbase)*DD;
    const float* EKg = g_EK + b*LL*DD;
    const float* Vg  = g_V  + b*LL*DD;

    // ---- init: iw = 1/(-2*w_all) ----
    if (tid < DD) {
        float wv = INV_SCALE + wdel[tid] + wsig[tid] + wthe[tid];
        iw[tid] = 1.0f / (-2.0f * wv);
    }
    __syncthreads();

    // ---- tables: EQ4[d4][q] = Eq*iw (folded), IW dup tables ----
    {   // 512 cells: q = tid&15, d4 = tid>>4
        int q  = tid & 15;
        int d4 = tid >> 4;
        float4 e = ((const float4*)EQg)[q*32 + d4];
        e.x *= iw[4*d4+0]; e.y *= iw[4*d4+1];
        e.z *= iw[4*d4+2]; e.w *= iw[4*d4+3];
        EQ4[d4*16 + q] = e;
    }
    if (tid < 32) {
        ulonglong2 ua; ua.x = pack2(iw[4*tid+0]); ua.y = pack2(iw[4*tid+1]);
        ulonglong2 ub; ub.x = pack2(iw[4*tid+2]); ub.y = pack2(iw[4*tid+3]);
        IWa[tid] = ua; IWb[tid] = ub;
    }
    // ordered by first kt-loop __syncthreads

    // ---------------- Phase 1: scores (8 tiles of 64 k) ----------------
    int q  = lane & 15;           // this lane's q row
    int kk = lane >> 4;           // sub k-pair
    int j  = 2*w + kk;            // this lane's k-pair within tile (0..31)
    const float4* EQcol = EQ4 + q;

    for (int kt = 0; kt < 8; ++kt) {
        __syncthreads();   // EK region free (covers table init on kt=0)
        {   // stage 64-k tile: cells (d4, jj): 1024 cells, 2 per thread
            const float4* EK4g = (const float4*)(EKg + kt*64*DD);
            #pragma unroll
            for (int it = 0; it < 2; ++it) {
                int cidx = it*512 + tid;       // 0..1023
                int d4 = cidx & 31;            // lane = d4 -> coalesced LDG
                int jj = cidx >> 5;            // 0..31
                float4 a  = EK4g[(2*jj)*32 + d4];
                float4 bb = EK4g[(2*jj+1)*32 + d4];
                ulonglong2 ua; ua.x = pack2two(a.x, bb.x); ua.y = pack2two(a.y, bb.y);
                ulonglong2 ub; ub.x = pack2two(a.z, bb.z); ub.y = pack2two(a.w, bb.w);
                EKa[d4*33 + jj] = ua;
                EKb[d4*33 + jj] = ub;
            }
        }
        __syncthreads();

        ull acc = 0ull;
        #pragma unroll 4
        for (int d4 = 0; d4 < 32; ++d4) {
            float4 eqv = EQcol[d4*16];
            ull eq0 = pack2(eqv.x), eq1 = pack2(eqv.y);
            ull eq2 = pack2(eqv.z), eq3 = pack2(eqv.w);
            ulonglong2 ia = IWa[d4];
            ulonglong2 ib = IWb[d4];
            ulonglong2 ka = EKa[d4*33 + j];
            ulonglong2 kb = EKb[d4*33 + j];
            ull D0 = ffma2(eq0, ka.x, ia.x);
            ull D1 = ffma2(eq1, ka.y, ia.y);
            ull D2 = ffma2(eq2, kb.x, ib.x);
            ull D3 = ffma2(eq3, kb.y, ib.y);
            ull n01 = fadd2(D0, D1);
            ull n23 = fadd2(D2, D3);
            ull P01 = fmul2(D0, D1);
            ull P23 = fmul2(D2, D3);
            ull N   = ffma2(n23, P01, fmul2(n01, P23));
            ull Dp  = fmul2(P01, P23);
            float2 df = unpack2(Dp);
            ull R = pack2two(frcp(df.x), frcp(df.y));
            acc = ffma2(N, R, acc);
        }
        *(float2*)(S + q*S_PITCH + kt*64 + 2*j) = unpack2(acc);
    }
    __syncthreads();   // rows assembled from all 16 warps

    // ---------------- Phase 2: softmax (warp w -> row w) ----------------
    {
        float* Srow = S + w*S_PITCH;
        float v[16];
        float m = -1e30f;
        #pragma unroll
        for (int i = 0; i < 16; ++i) { v[i] = Srow[i*32 + lane]; m = fmaxf(m, v[i]); }
        #pragma unroll
        for (int s = 16; s > 0; s >>= 1) m = fmaxf(m, __shfl_xor_sync(0xffffffffu, m, s));
        float sum = 0.f;
        #pragma unroll
        for (int i = 0; i < 16; ++i) {
            float e = __expf(v[i] - m);
            Srow[i*32 + lane] = e;
            sum += e;
        }
        #pragma unroll
        for (int s = 16; s > 0; s >>= 1) sum += __shfl_xor_sync(0xffffffffu, sum, s);
        if (lane == 0) rinv[w] = 1.0f / sum;
    }

    // ---------------- Phase 3: O = P @ V (FFMA2) ----------------
    int r0  = (w & 7) * 2;
    int dh  = w >> 3;
    int dA  = dh*64 + lane;
    ull acc3[2][2] = {{0,0},{0,0}};
    const ull* Vp = (const ull*)(sm + SM_EKA);   // [32][128] : Vp[k2][d]

    for (int kt = 0; kt < 8; ++kt) {             // 8 tiles of 64 k
        __syncthreads();   // previous tile consumed (kt=0: softmax done)
        {   // stage V pairs: 1024 cells, 2 per thread
            const float4* Va = (const float4*)(Vg + kt*64*DD);
            float2* Vp2 = (float2*)(sm + SM_EKA);
            #pragma unroll
            for (int it = 0; it < 2; ++it) {
                int cidx = it*512 + tid;       // 0..1023
                int d4 = cidx & 31;
                int k2 = cidx >> 5;
                float4 a  = Va[(2*k2)*32 + d4];
                float4 bb = Va[(2*k2+1)*32 + d4];
                Vp2[k2*128 + 4*d4 + 0] = make_float2(a.x, bb.x);
                Vp2[k2*128 + 4*d4 + 1] = make_float2(a.y, bb.y);
                Vp2[k2*128 + 4*d4 + 2] = make_float2(a.z, bb.z);
                Vp2[k2*128 + 4*d4 + 3] = make_float2(a.w, bb.w);
            }
        }
        __syncthreads();

        const float* Sb = S + kt*64;
        #pragma unroll 4
        for (int k2 = 0; k2 < 32; ++k2) {
            ull p0 = *(const ull*)(Sb + (r0+0)*S_PITCH + 2*k2);
            ull p1 = *(const ull*)(Sb + (r0+1)*S_PITCH + 2*k2);
            ull v0 = Vp[k2*128 + dA];
            ull v1 = Vp[k2*128 + dA + 32];
            acc3[0][0] = ffma2(p0, v0, acc3[0][0]);  acc3[0][1] = ffma2(p0, v1, acc3[0][1]);
            acc3[1][0] = ffma2(p1, v0, acc3[1][0]);  acc3[1][1] = ffma2(p1, v1, acc3[1][1]);
        }
    }

    #pragma unroll
    for (int i = 0; i < 2; ++i) {
        float inv = rinv[r0 + i];
        float2 eo = unpack2(acc3[i][0]);
        float2 e1 = unpack2(acc3[i][1]);
        float* orow = out + (size_t)(b*LL + qbase + r0 + i)*DD;
        orow[dA]      = (eo.x + eo.y) * inv;
        orow[dA + 32] = (e1.x + e1.y) * inv;
    }
}

// =====================================================================
extern "C" void kernel_launch(void* const* d_in, const int* in_sizes, int n_in,
                              void* d_out, int out_size)
{
    const float* query = (const float*)d_in[0];
    const float* key   = (const float*)d_in[1];
    const float* value = (const float*)d_in[2];
    const float* Wq    = (const float*)d_in[3];
    const float* bq    = (const float*)d_in[4];
    const float* Wk    = (const float*)d_in[5];
    const float* bk    = (const float*)d_in[6];
    const float* Wv    = (const float*)d_in[7];
    const float* bv    = (const float*)d_in[8];
    const float* wdel  = (const float*)d_in[9];
    const float* wsig  = (const float*)d_in[11];
    const float* wthe  = (const float*)d_in[13];
    float* out = (float*)d_out;

    const int PROJ_SMEM = PROJ_SMEM_FLOATS * (int)sizeof(float);   // 132608
    const int ATTN_SMEM = ATTN_SMEM_FLOATS * (int)sizeof(float);   // 76096

    cudaFuncSetAttribute(proj_kernel, cudaFuncAttributeMaxDynamicSharedMemorySize, PROJ_SMEM);
    cudaFuncSetAttribute(attn_kernel, cudaFuncAttributeMaxDynamicSharedMemorySize, ATTN_SMEM);

    proj_kernel<<<96, 256, PROJ_SMEM>>>(query, key, value, Wq, bq, Wk, bk, Wv, bv);
    attn_kernel<<<BB*32, 512, ATTN_SMEM>>>(wdel, wsig, wthe, out);
}

// round 16
// speedup vs baseline: 1.0550x; 1.0550x over previous
#include <cuda_runtime.h>

#define BB 8
#define LL 512
#define DD 128
#define INV_SCALE 0.08838834764831843f   // 1/sqrt(128)

typedef unsigned long long ull;

// ---- scratch (no cudaMalloc allowed) ----
__device__ float g_EQ[BB*LL*DD];   // exp(2*Qproj)
__device__ float g_EK[BB*LL*DD];   // exp(2*Kproj)
__device__ float g_V [BB*LL*DD];

__device__ __forceinline__ float frcp(float x) {
    float y;
    asm("rcp.approx.f32 %0, %1;" : "=f"(y) : "f"(x));
    return y;
}
__device__ __forceinline__ ull ffma2(ull a, ull b, ull c) {
    ull d;
    asm("fma.rn.f32x2 %0, %1, %2, %3;" : "=l"(d) : "l"(a), "l"(b), "l"(c));
    return d;
}
__device__ __forceinline__ ull fmul2(ull a, ull b) {
    ull d;
    asm("mul.rn.f32x2 %0, %1, %2;" : "=l"(d) : "l"(a), "l"(b));
    return d;
}
__device__ __forceinline__ ull fadd2(ull a, ull b) {
    ull d;
    asm("add.rn.f32x2 %0, %1, %2;" : "=l"(d) : "l"(a), "l"(b));
    return d;
}
__device__ __forceinline__ ull pack2(float x) {
    ull d;
    asm("mov.b64 %0, {%1, %1};" : "=l"(d) : "f"(x));
    return d;
}
__device__ __forceinline__ ull pack2two(float x, float y) {
    ull d;
    asm("mov.b64 %0, {%1, %2};" : "=l"(d) : "f"(x), "f"(y));
    return d;
}
__device__ __forceinline__ float2 unpack2(ull v) {
    float2 r;
    asm("mov.b64 {%0, %1}, %2;" : "=f"(r.x), "=f"(r.y) : "l"(v));
    return r;
}

// =====================================================================
// Projection: 96 blocks, 128x128 tiles, NOW 512 threads (16 warps,
// 4 warps/SMSP for latency hiding), thread tile 4x8, FFMA2.
// Conflict-free Wt staging (lane = r) — the fix R5's 512-thr attempt
// lacked.  Epilogue: exp(2x) for Q,K; identity for V.
// smem: Xs[128][129] + Wt[128][130] = 132608 B
// =====================================================================
#define XS_PITCH 129
#define WT_PITCH 130
#define PROJ_SMEM_FLOATS (128*XS_PITCH + 128*WT_PITCH)

__global__ void __launch_bounds__(512) proj_kernel(
    const float* __restrict__ Xq, const float* __restrict__ Xk, const float* __restrict__ Xv,
    const float* __restrict__ Wq, const float* __restrict__ bq,
    const float* __restrict__ Wk, const float* __restrict__ bk,
    const float* __restrict__ Wv, const float* __restrict__ bv)
{
    extern __shared__ float sm[];
    float* Xs = sm;                    // [128][129]
    float* Wt = sm + 128*XS_PITCH;     // [128][130]  Wt[d][c]
    __shared__ float bs[DD];

    int bx  = blockIdx.x;
    int mat = bx >> 5;
    int rt  = bx & 31;
    const float *X, *W, *bias;
    float* out;
    if (mat == 0)      { X = Xq; W = Wq; bias = bq; out = g_EQ; }
    else if (mat == 1) { X = Xk; W = Wk; bias = bk; out = g_EK; }
    else               { X = Xv; W = Wv; bias = bv; out = g_V;  }

    int tid = threadIdx.x;
    const float4* Xg = (const float4*)(X + rt*128*DD);
    const float4* Wg = (const float4*)W;
    #pragma unroll
    for (int it = 0; it < 8; ++it) {
        int idx = it*512 + tid;           // 0..4095
        // X: coalesced LDG, contiguous STS
        {
            int d4  = idx & 31;
            int r   = idx >> 5;
            float4 xv = Xg[idx];
            float* xd = Xs + r*XS_PITCH + 4*d4;
            xd[0] = xv.x; xd[1] = xv.y; xd[2] = xv.z; xd[3] = xv.w;
        }
        // W: lane = r-low -> conflict-free transposed STS (L2-resident gather)
        {
            int rlo = idx & 31;
            int hi  = idx >> 5;            // 0..127
            int d4  = hi & 31;
            int r   = ((hi >> 5) << 5) + rlo;   // lane-stride 1
            float4 wv = Wg[r*32 + d4];
            Wt[(4*d4+0)*WT_PITCH + r] = wv.x;
            Wt[(4*d4+1)*WT_PITCH + r] = wv.y;
            Wt[(4*d4+2)*WT_PITCH + r] = wv.z;
            Wt[(4*d4+3)*WT_PITCH + r] = wv.w;
        }
    }
    if (tid < DD) bs[tid] = bias[tid];
    __syncthreads();

    int tr = tid >> 4;     // 0..31 (4-row group)
    int tc = tid & 15;     // 0..15 (8-col group)
    const float* xb = Xs + (tr*4)*XS_PITCH;
    const float* wb = Wt + tc*8;

    ull acc[4][4];
    #pragma unroll
    for (int i = 0; i < 4; ++i)
        #pragma unroll
        for (int j = 0; j < 4; ++j) acc[i][j] = 0ull;

    #pragma unroll 4
    for (int d = 0; d < DD; ++d) {
        float xs[4]; ull xp[4]; ull wp[4];
        #pragma unroll
        for (int i = 0; i < 4; ++i) xs[i] = xb[i*XS_PITCH + d];
        #pragma unroll
        for (int j = 0; j < 4; ++j) wp[j] = *(const ull*)(wb + d*WT_PITCH + 2*j);
        #pragma unroll
        for (int i = 0; i < 4; ++i) xp[i] = pack2(xs[i]);
        #pragma unroll
        for (int i = 0; i < 4; ++i)
            #pragma unroll
            for (int j = 0; j < 4; ++j) acc[i][j] = ffma2(xp[i], wp[j], acc[i][j]);
    }

    int rbase = rt*128 + tr*4;
    #pragma unroll
    for (int i = 0; i < 4; ++i) {
        float* orow = out + (rbase + i)*DD + tc*8;
        #pragma unroll
        for (int j = 0; j < 4; ++j) {
            float2 v = unpack2(acc[i][j]);
            float o0 = v.x + bs[tc*8 + 2*j+0];
            float o1 = v.y + bs[tc*8 + 2*j+1];
            if (mat != 2) { o0 = __expf(2.0f*o0); o1 = __expf(2.0f*o1); }
            orow[2*j+0] = o0;
            orow[2*j+1] = o1;
        }
    }
}

// =====================================================================
// Attention — R13 verbatim (measured 87.2 us, regs 55).
// Block = (batch b, 32-q tile), 1024 threads (32 warps), lane = q.
// Phase 1: iw_d = 1/(-2 w_d), Eq''_d = Eq_d*iw_d (in EQ4 table).
//   D_d = ffma2(dup(Eq''_d), ekpair_d, dup(iw_d)) = (1+Eq*Ek)/(-2w)
//   score(shifted) = sum_d 1/D_d; per d-quad:
//     N=(D0+D1)*P23+(D2+D3)*P01, Dp=P01*P23, acc += N*rcp(Dp)
//   Warp w owns k-pairs (2w, 2w+1) of each 128-k tile (4 tiles).
// Phase 2: warp-per-row softmax.
// Phase 3: O = P @ V, FFMA2.
// =====================================================================
#define S_PITCH 516
#define SM_S    0
#define SM_EKA  16512
#define SM_EKB  24832
#define SM_EQ4  33152
#define SM_IWA  37248
#define SM_IWB  37376
#define SM_RINV 37504
#define ATTN_SMEM_FLOATS 37536    // 150144 B

__global__ void __launch_bounds__(1024) attn_kernel(
    const float* __restrict__ wdel, const float* __restrict__ wsig,
    const float* __restrict__ wthe, float* __restrict__ out)
{
    extern __shared__ float sm[];
    float*      S    = sm + SM_S;
    ulonglong2* EKa  = (ulonglong2*)(sm + SM_EKA);   // [32][65]
    ulonglong2* EKb  = (ulonglong2*)(sm + SM_EKB);   // [32][65]
    float4*     EQ4  = (float4*)(sm + SM_EQ4);       // [d4][q]
    ulonglong2* IWa  = (ulonglong2*)(sm + SM_IWA);
    ulonglong2* IWb  = (ulonglong2*)(sm + SM_IWB);
    float*      rinv = sm + SM_RINV;
    float*      iw   = sm + SM_S;                    // temp during init

    int tid  = threadIdx.x;
    int w    = tid >> 5;
    int lane = tid & 31;
    int b    = blockIdx.x >> 4;
    int qt   = blockIdx.x & 15;
    int qbase = qt * 32;

    const float* EQg = g_EQ + (b*LL + qbase)*DD;
    const float* EKg = g_EK + b*LL*DD;
    const float* Vg  = g_V  + b*LL*DD;

    // ---- init: iw = 1/(-2*w_all) ----
    if (tid < DD) {
        float wv = INV_SCALE + wdel[tid] + wsig[tid] + wthe[tid];
        iw[tid] = 1.0f / (-2.0f * wv);
    }
    __syncthreads();

    // ---- tables: EQ4[d4][q] = Eq*iw (folded), IW dup tables ----
    {
        int q  = tid & 31;
        int d4 = tid >> 5;
        float4 e = ((const float4*)EQg)[q*32 + d4];
        e.x *= iw[4*d4+0]; e.y *= iw[4*d4+1];
        e.z *= iw[4*d4+2]; e.w *= iw[4*d4+3];
        EQ4[d4*32 + q] = e;
    }
    if (tid < 32) {
        ulonglong2 ua; ua.x = pack2(iw[4*tid+0]); ua.y = pack2(iw[4*tid+1]);
        ulonglong2 ub; ub.x = pack2(iw[4*tid+2]); ub.y = pack2(iw[4*tid+3]);
        IWa[tid] = ua; IWb[tid] = ub;
    }
    // ordered by first kt-loop __syncthreads

    // ---------------- Phase 1: scores ----------------
    int j0 = 2*w;                 // this warp's k-pair indices (j0, j0+1)

    for (int kt = 0; kt < 4; ++kt) {          // 4 tiles of 128 k
        __syncthreads();   // EK region free (covers table init on kt=0)
        {   // stage 128-k tile: cells (d4, j), j = k-pair 0..63
            const float4* EK4g = (const float4*)(EKg + kt*128*DD);
            #pragma unroll
            for (int it = 0; it < 2; ++it) {
                int cidx = it*1024 + tid;      // 0..2047
                int d4 = cidx & 31;
                int j  = cidx >> 5;            // 0..63
                float4 a  = EK4g[(2*j)*32 + d4];
                float4 bb = EK4g[(2*j+1)*32 + d4];
                ulonglong2 ua; ua.x = pack2two(a.x, bb.x); ua.y = pack2two(a.y, bb.y);
                ulonglong2 ub; ub.x = pack2two(a.z, bb.z); ub.y = pack2two(a.w, bb.w);
                EKa[d4*65 + j] = ua;
                EKb[d4*65 + j] = ub;
            }
        }
        __syncthreads();

        ull acc0 = 0ull, acc1 = 0ull;
        #pragma unroll 4
        for (int d4 = 0; d4 < 32; ++d4) {
            float4 eqv = EQ4[d4*32 + lane];
            ull eq0 = pack2(eqv.x), eq1 = pack2(eqv.y);
            ull eq2 = pack2(eqv.z), eq3 = pack2(eqv.w);
            ulonglong2 ia = IWa[d4];
            ulonglong2 ib = IWb[d4];
            #pragma unroll
            for (int jj = 0; jj < 2; ++jj) {
                ulonglong2 ka = EKa[d4*65 + j0 + jj];
                ulonglong2 kb = EKb[d4*65 + j0 + jj];
                ull D0 = ffma2(eq0, ka.x, ia.x);
                ull D1 = ffma2(eq1, ka.y, ia.y);
                ull D2 = ffma2(eq2, kb.x, ib.x);
                ull D3 = ffma2(eq3, kb.y, ib.y);
                ull n01 = fadd2(D0, D1);
                ull n23 = fadd2(D2, D3);
                ull P01 = fmul2(D0, D1);
                ull P23 = fmul2(D2, D3);
                ull N   = ffma2(n23, P01, fmul2(n01, P23));
                ull Dp  = fmul2(P01, P23);
                float2 df = unpack2(Dp);
                ull R = pack2two(frcp(df.x), frcp(df.y));
                if (jj == 0) acc0 = ffma2(N, R, acc0);
                else         acc1 = ffma2(N, R, acc1);
            }
        }
        float2 s0 = unpack2(acc0);
        float2 s1 = unpack2(acc1);
        *(float4*)(S + lane*S_PITCH + kt*128 + 4*w) = make_float4(s0.x, s0.y, s1.x, s1.y);
    }
    __syncthreads();   // each row assembled from all 32 warps

    // ---------------- Phase 2: softmax ----------------
    {
        float* Srow = S + w*S_PITCH;
        float v[16];
        float m = -1e30f;
        #pragma unroll
        for (int i = 0; i < 16; ++i) { v[i] = Srow[i*32 + lane]; m = fmaxf(m, v[i]); }
        #pragma unroll
        for (int s = 16; s > 0; s >>= 1) m = fmaxf(m, __shfl_xor_sync(0xffffffffu, m, s));
        float sum = 0.f;
        #pragma unroll
        for (int i = 0; i < 16; ++i) {
            float e = __expf(v[i] - m);
            Srow[i*32 + lane] = e;
            sum += e;
        }
        #pragma unroll
        for (int s = 16; s > 0; s >>= 1) sum += __shfl_xor_sync(0xffffffffu, sum, s);
        if (lane == 0) rinv[w] = 1.0f / sum;
    }

    // ---------------- Phase 3: O = P @ V (FFMA2) ----------------
    int r0  = (w & 15) * 2;
    int dh  = w >> 4;
    int dA  = dh*64 + lane;
    ull acc3[2][2] = {{0,0},{0,0}};
    const ull* Vp = (const ull*)(sm + SM_EKA);   // [32][128] : Vp[k2][d]

    for (int kt = 0; kt < 8; ++kt) {             // 8 tiles of 64 k
        __syncthreads();   // previous tile consumed (kt=0: softmax done)
        {
            const float4* Va = (const float4*)(Vg + kt*64*DD);
            float2* Vp2 = (float2*)(sm + SM_EKA);
            int k2 = tid >> 5, d4 = tid & 31;
            float4 a  = Va[(2*k2)*32 + d4];
            float4 bb = Va[(2*k2+1)*32 + d4];
            Vp2[k2*128 + 4*d4 + 0] = make_float2(a.x, bb.x);
            Vp2[k2*128 + 4*d4 + 1] = make_float2(a.y, bb.y);
            Vp2[k2*128 + 4*d4 + 2] = make_float2(a.z, bb.z);
            Vp2[k2*128 + 4*d4 + 3] = make_float2(a.w, bb.w);
        }
        __syncthreads();

        const float* Sb = S + kt*64;
        #pragma unroll 4
        for (int k2 = 0; k2 < 32; ++k2) {
            ull p0 = *(const ull*)(Sb + (r0+0)*S_PITCH + 2*k2);
            ull p1 = *(const ull*)(Sb + (r0+1)*S_PITCH + 2*k2);
            ull v0 = Vp[k2*128 + dA];
            ull v1 = Vp[k2*128 + dA + 32];
            acc3[0][0] = ffma2(p0, v0, acc3[0][0]);  acc3[0][1] = ffma2(p0, v1, acc3[0][1]);
            acc3[1][0] = ffma2(p1, v0, acc3[1][0]);  acc3[1][1] = ffma2(p1, v1, acc3[1][1]);
        }
    }

    #pragma unroll
    for (int i = 0; i < 2; ++i) {
        float inv = rinv[r0 + i];
        float2 eo = unpack2(acc3[i][0]);
        float2 e1 = unpack2(acc3[i][1]);
        float* orow = out + (size_t)(b*LL + qbase + r0 + i)*DD;
        orow[dA]      = (eo.x + eo.y) * inv;
        orow[dA + 32] = (e1.x + e1.y) * inv;
    }
}

// =====================================================================
extern "C" void kernel_launch(void* const* d_in, const int* in_sizes, int n_in,
                              void* d_out, int out_size)
{
    const float* query = (const float*)d_in[0];
    const float* key   = (const float*)d_in[1];
    const float* value = (const float*)d_in[2];
    const float* Wq    = (const float*)d_in[3];
    const float* bq    = (const float*)d_in[4];
    const float* Wk    = (const float*)d_in[5];
    const float* bk    = (const float*)d_in[6];
    const float* Wv    = (const float*)d_in[7];
    const float* bv    = (const float*)d_in[8];
    const float* wdel  = (const float*)d_in[9];
    const float* wsig  = (const float*)d_in[11];
    const float* wthe  = (const float*)d_in[13];
    float* out = (float*)d_out;

    const int PROJ_SMEM = PROJ_SMEM_FLOATS * (int)sizeof(float);   // 132608
    const int ATTN_SMEM = ATTN_SMEM_FLOATS * (int)sizeof(float);   // 150144

    cudaFuncSetAttribute(proj_kernel, cudaFuncAttributeMaxDynamicSharedMemorySize, PROJ_SMEM);
    cudaFuncSetAttribute(attn_kernel, cudaFuncAttributeMaxDynamicSharedMemorySize, ATTN_SMEM);

    proj_kernel<<<96, 512, PROJ_SMEM>>>(query, key, value, Wq, bq, Wk, bk, Wv, bv);
    attn_kernel<<<BB*16, 1024, ATTN_SMEM>>>(wdel, wsig, wthe, out);
}

// round 17
// speedup vs baseline: 1.1065x; 1.0488x over previous
#include <cuda_runtime.h>

#define BB 8
#define LL 512
#define DD 128
#define INV_SCALE 0.08838834764831843f   // 1/sqrt(128)

typedef unsigned long long ull;

// ---- scratch (no cudaMalloc allowed) ----
__device__ float g_EQ[BB*LL*DD];   // exp(2*Qproj)
__device__ float g_EK[BB*LL*DD];   // exp(2*Kproj)
__device__ float g_V [BB*LL*DD];

__device__ __forceinline__ float frcp(float x) {
    float y;
    asm("rcp.approx.f32 %0, %1;" : "=f"(y) : "f"(x));
    return y;
}
__device__ __forceinline__ ull ffma2(ull a, ull b, ull c) {
    ull d;
    asm("fma.rn.f32x2 %0, %1, %2, %3;" : "=l"(d) : "l"(a), "l"(b), "l"(c));
    return d;
}
__device__ __forceinline__ ull fmul2(ull a, ull b) {
    ull d;
    asm("mul.rn.f32x2 %0, %1, %2;" : "=l"(d) : "l"(a), "l"(b));
    return d;
}
__device__ __forceinline__ ull fadd2(ull a, ull b) {
    ull d;
    asm("add.rn.f32x2 %0, %1, %2;" : "=l"(d) : "l"(a), "l"(b));
    return d;
}
__device__ __forceinline__ ull pack2(float x) {
    ull d;
    asm("mov.b64 %0, {%1, %1};" : "=l"(d) : "f"(x));
    return d;
}
__device__ __forceinline__ ull pack2two(float x, float y) {
    ull d;
    asm("mov.b64 %0, {%1, %2};" : "=l"(d) : "f"(x), "f"(y));
    return d;
}
__device__ __forceinline__ float2 unpack2(ull v) {
    float2 r;
    asm("mov.b64 {%0, %1}, %2;" : "=f"(r.x), "=f"(r.y) : "l"(v));
    return r;
}

// =====================================================================
// Projection — R13 verbatim (measured ~23 us): 96 blocks, 128x128
// tiles, 256 threads, 8x8 thread tile, FFMA2.
// Epilogue: exp(2x) for Q,K; identity for V.
// =====================================================================
#define XS_PITCH 129
#define WT_PITCH 130
#define PROJ_SMEM_FLOATS (128*XS_PITCH + 128*WT_PITCH)

__global__ void __launch_bounds__(256) proj_kernel(
    const float* __restrict__ Xq, const float* __restrict__ Xk, const float* __restrict__ Xv,
    const float* __restrict__ Wq, const float* __restrict__ bq,
    const float* __restrict__ Wk, const float* __restrict__ bk,
    const float* __restrict__ Wv, const float* __restrict__ bv)
{
    extern __shared__ float sm[];
    float* Xs = sm;                    // [128][129]
    float* Wt = sm + 128*XS_PITCH;     // [128][130]  Wt[d][c]
    __shared__ float bs[DD];

    int bx  = blockIdx.x;
    int mat = bx >> 5;
    int rt  = bx & 31;
    const float *X, *W, *bias;
    float* out;
    if (mat == 0)      { X = Xq; W = Wq; bias = bq; out = g_EQ; }
    else if (mat == 1) { X = Xk; W = Wk; bias = bk; out = g_EK; }
    else               { X = Xv; W = Wv; bias = bv; out = g_V;  }

    int tid = threadIdx.x;
    const float4* Xg = (const float4*)(X + rt*128*DD);
    const float4* Wg = (const float4*)W;
    #pragma unroll
    for (int it = 0; it < 16; ++it) {
        int idx = it*256 + tid;           // 0..4095
        {
            int d4  = idx & 31;
            int r   = idx >> 5;
            float4 xv = Xg[idx];
            float* xd = Xs + r*XS_PITCH + 4*d4;
            xd[0] = xv.x; xd[1] = xv.y; xd[2] = xv.z; xd[3] = xv.w;
        }
        {
            int rlo = idx & 31;
            int hi  = idx >> 5;
            int d4  = hi & 31;
            int r   = ((hi >> 5) << 5) + rlo;
            float4 wv = Wg[r*32 + d4];
            Wt[(4*d4+0)*WT_PITCH + r] = wv.x;
            Wt[(4*d4+1)*WT_PITCH + r] = wv.y;
            Wt[(4*d4+2)*WT_PITCH + r] = wv.z;
            Wt[(4*d4+3)*WT_PITCH + r] = wv.w;
        }
    }
    if (tid < DD) bs[tid] = bias[tid];
    __syncthreads();

    int tr = tid >> 4;
    int tc = tid & 15;
    const float* xb = Xs + (tr*8)*XS_PITCH;
    const float* wb = Wt + tc*8;

    ull acc[8][4];
    #pragma unroll
    for (int i = 0; i < 8; ++i)
        #pragma unroll
        for (int j = 0; j < 4; ++j) acc[i][j] = 0ull;

    #pragma unroll 4
    for (int d = 0; d < DD; ++d) {
        float xs[8]; ull xp[8]; ull wp[4];
        #pragma unroll
        for (int i = 0; i < 8; ++i) xs[i] = xb[i*XS_PITCH + d];
        #pragma unroll
        for (int j = 0; j < 4; ++j) wp[j] = *(const ull*)(wb + d*WT_PITCH + 2*j);
        #pragma unroll
        for (int i = 0; i < 8; ++i) xp[i] = pack2(xs[i]);
        #pragma unroll
        for (int i = 0; i < 8; ++i)
            #pragma unroll
            for (int j = 0; j < 4; ++j) acc[i][j] = ffma2(xp[i], wp[j], acc[i][j]);
    }

    int rbase = rt*128 + tr*8;
    #pragma unroll
    for (int i = 0; i < 8; ++i) {
        float* orow = out + (rbase + i)*DD + tc*8;
        #pragma unroll
        for (int j = 0; j < 4; ++j) {
            float2 v = unpack2(acc[i][j]);
            float o0 = v.x + bs[tc*8 + 2*j+0];
            float o1 = v.y + bs[tc*8 + 2*j+1];
            if (mat != 2) { o0 = __expf(2.0f*o0); o1 = __expf(2.0f*o1); }
            orow[2*j+0] = o0;
            orow[2*j+1] = o1;
        }
    }
}

// =====================================================================
// Attention — R13 structure with conflict-free staging:
//   EK tile stored RAW (EKr[k][d4] float4, linear copy); the (k,k+1)
//   pairing pack2two moved into the reader where both row-quads are
//   warp-uniform LDS broadcasts (same LDS count, fewer total packs).
//   V staged one (k2,d) cell/thread into pitch-129 ull Vp[k2][d]:
//   coalesced LDG.32 + conflict-free STS.64.
// Block = (batch b, 32-q tile), 1024 threads (32 warps), lane = q.
// Phase 1: iw_d = 1/(-2 w_d), Eq''_d = Eq_d*iw_d (EQ4 table).
//   D_d = ffma2(dup(Eq''_d), (Ek[2j],Ek[2j+1])_d, dup(iw_d))
//   score(shifted) = sum_d 1/D_d; per d-quad:
//     N=(D0+D1)*P23+(D2+D3)*P01, Dp=P01*P23, acc += N*rcp(Dp)
//   Warp w owns k-pairs (2w, 2w+1) of each 128-k tile (4 tiles).
// Phase 2: warp-per-row softmax.
// Phase 3: O = P @ V, FFMA2, Vp pitch 129.
// smem (floats):
//   S[32][516]          @ 0       16512  (first 128 reused as iw temp)
//   EKr[128][32] float4 @ 16512   16384  (raw tile; Vp[32][129]ull reuses)
//   EQ4[32][32] float4  @ 33152    4096
//   IWa[32] ull2        @ 37248     128
//   IWb[32] ull2        @ 37376     128
//   rinv[32]            @ 37504
// =====================================================================
#define S_PITCH 516
#define SM_S    0
#define SM_EKR  16512
#define SM_EQ4  33152
#define SM_IWA  37248
#define SM_IWB  37376
#define SM_RINV 37504
#define ATTN_SMEM_FLOATS 37536    // 150144 B
#define VP_PITCH 129              // ull units

__global__ void __launch_bounds__(1024) attn_kernel(
    const float* __restrict__ wdel, const float* __restrict__ wsig,
    const float* __restrict__ wthe, float* __restrict__ out)
{
    extern __shared__ float sm[];
    float*      S    = sm + SM_S;
    float4*     EKr  = (float4*)(sm + SM_EKR);       // [128 k][32 d4]
    float4*     EQ4  = (float4*)(sm + SM_EQ4);       // [d4][q]
    ulonglong2* IWa  = (ulonglong2*)(sm + SM_IWA);
    ulonglong2* IWb  = (ulonglong2*)(sm + SM_IWB);
    float*      rinv = sm + SM_RINV;
    float*      iw   = sm + SM_S;                    // temp during init

    int tid  = threadIdx.x;
    int w    = tid >> 5;
    int lane = tid & 31;
    int b    = blockIdx.x >> 4;
    int qt   = blockIdx.x & 15;
    int qbase = qt * 32;

    const float* EQg = g_EQ + (b*LL + qbase)*DD;
    const float* EKg = g_EK + b*LL*DD;
    const float* Vg  = g_V  + b*LL*DD;

    // ---- init: iw = 1/(-2*w_all) ----
    if (tid < DD) {
        float wv = INV_SCALE + wdel[tid] + wsig[tid] + wthe[tid];
        iw[tid] = 1.0f / (-2.0f * wv);
    }
    __syncthreads();

    // ---- tables: EQ4[d4][q] = Eq*iw (folded), IW dup tables ----
    {
        int q  = tid & 31;
        int d4 = tid >> 5;
        float4 e = ((const float4*)EQg)[q*32 + d4];
        e.x *= iw[4*d4+0]; e.y *= iw[4*d4+1];
        e.z *= iw[4*d4+2]; e.w *= iw[4*d4+3];
        EQ4[d4*32 + q] = e;
    }
    if (tid < 32) {
        ulonglong2 ua; ua.x = pack2(iw[4*tid+0]); ua.y = pack2(iw[4*tid+1]);
        ulonglong2 ub; ub.x = pack2(iw[4*tid+2]); ub.y = pack2(iw[4*tid+3]);
        IWa[tid] = ua; IWb[tid] = ub;
    }
    // ordered by first kt-loop __syncthreads

    // ---------------- Phase 1: scores ----------------
    int j0 = 2*w;                 // this warp's k-pair indices (j0, j0+1)

    for (int kt = 0; kt < 4; ++kt) {          // 4 tiles of 128 k
        __syncthreads();   // EKr region free (covers table init on kt=0)
        {   // stage raw 128-k tile: linear copy, coalesced + conflict-free
            const float4* EK4g = (const float4*)(EKg + kt*128*DD);
            #pragma unroll
            for (int it = 0; it < 4; ++it)
                EKr[it*1024 + tid] = EK4g[it*1024 + tid];
        }
        __syncthreads();

        ull acc0 = 0ull, acc1 = 0ull;
        #pragma unroll 4
        for (int d4 = 0; d4 < 32; ++d4) {
            float4 eqv = EQ4[d4*32 + lane];
            ull eq0 = pack2(eqv.x), eq1 = pack2(eqv.y);
            ull eq2 = pack2(eqv.z), eq3 = pack2(eqv.w);
            ulonglong2 ia = IWa[d4];
            ulonglong2 ib = IWb[d4];
            #pragma unroll
            for (int jj = 0; jj < 2; ++jj) {
                float4 ra = EKr[(2*(j0+jj)  )*32 + d4];   // row 2j   (uniform)
                float4 rb = EKr[(2*(j0+jj)+1)*32 + d4];   // row 2j+1 (uniform)
                ull kax = pack2two(ra.x, rb.x);
                ull kay = pack2two(ra.y, rb.y);
                ull kbx = pack2two(ra.z, rb.z);
                ull kby = pack2two(ra.w, rb.w);
                ull D0 = ffma2(eq0, kax, ia.x);
                ull D1 = ffma2(eq1, kay, ia.y);
                ull D2 = ffma2(eq2, kbx, ib.x);
                ull D3 = ffma2(eq3, kby, ib.y);
                ull n01 = fadd2(D0, D1);
                ull n23 = fadd2(D2, D3);
                ull P01 = fmul2(D0, D1);
                ull P23 = fmul2(D2, D3);
                ull N   = ffma2(n23, P01, fmul2(n01, P23));
                ull Dp  = fmul2(P01, P23);
                float2 df = unpack2(Dp);
                ull R = pack2two(frcp(df.x), frcp(df.y));
                if (jj == 0) acc0 = ffma2(N, R, acc0);
                else         acc1 = ffma2(N, R, acc1);
            }
        }
        float2 s0 = unpack2(acc0);
        float2 s1 = unpack2(acc1);
        *(float4*)(S + lane*S_PITCH + kt*128 + 4*w) = make_float4(s0.x, s0.y, s1.x, s1.y);
    }
    __syncthreads();   // each row assembled from all 32 warps

    // ---------------- Phase 2: softmax ----------------
    {
        float* Srow = S + w*S_PITCH;
        float v[16];
        float m = -1e30f;
        #pragma unroll
        for (int i = 0; i < 16; ++i) { v[i] = Srow[i*32 + lane]; m = fmaxf(m, v[i]); }
        #pragma unroll
        for (int s = 16; s > 0; s >>= 1) m = fmaxf(m, __shfl_xor_sync(0xffffffffu, m, s));
        float sum = 0.f;
        #pragma unroll
        for (int i = 0; i < 16; ++i) {
            float e = __expf(v[i] - m);
            Srow[i*32 + lane] = e;
            sum += e;
        }
        #pragma unroll
        for (int s = 16; s > 0; s >>= 1) sum += __shfl_xor_sync(0xffffffffu, sum, s);
        if (lane == 0) rinv[w] = 1.0f / sum;
    }

    // ---------------- Phase 3: O = P @ V (FFMA2) ----------------
    int r0  = (w & 15) * 2;
    int dh  = w >> 4;
    int dA  = dh*64 + lane;
    ull acc3[2][2] = {{0,0},{0,0}};
    ull* Vp = (ull*)(sm + SM_EKR);   // [32 k2][VP_PITCH] : Vp[k2][d]

    for (int kt = 0; kt < 8; ++kt) {             // 8 tiles of 64 k
        __syncthreads();   // previous tile consumed (kt=0: softmax done)
        {   // stage V pairs: one (k2,d) cell per thread, 4 cells each
            const float* Vrow = Vg + kt*64*DD;
            #pragma unroll
            for (int it = 0; it < 4; ++it) {
                int c  = it*1024 + tid;      // 0..4095
                int d  = c & 127;            // lane stride 1 -> coalesced/conflict-free
                int k2 = c >> 7;
                float v0 = Vrow[(2*k2  )*DD + d];
                float v1 = Vrow[(2*k2+1)*DD + d];
                Vp[k2*VP_PITCH + d] = pack2two(v0, v1);
            }
        }
        __syncthreads();

        const float* Sb = S + kt*64;
        #pragma unroll 4
        for (int k2 = 0; k2 < 32; ++k2) {
            ull p0 = *(const ull*)(Sb + (r0+0)*S_PITCH + 2*k2);
            ull p1 = *(const ull*)(Sb + (r0+1)*S_PITCH + 2*k2);
            ull v0 = Vp[k2*VP_PITCH + dA];
            ull v1 = Vp[k2*VP_PITCH + dA + 32];
            acc3[0][0] = ffma2(p0, v0, acc3[0][0]);  acc3[0][1] = ffma2(p0, v1, acc3[0][1]);
            acc3[1][0] = ffma2(p1, v0, acc3[1][0]);  acc3[1][1] = ffma2(p1, v1, acc3[1][1]);
        }
    }

    #pragma unroll
    for (int i = 0; i < 2; ++i) {
        float inv = rinv[r0 + i];
        float2 eo = unpack2(acc3[i][0]);
        float2 e1 = unpack2(acc3[i][1]);
        float* orow = out + (size_t)(b*LL + qbase + r0 + i)*DD;
        orow[dA]      = (eo.x + eo.y) * inv;
        orow[dA + 32] = (e1.x + e1.y) * inv;
    }
}

// =====================================================================
extern "C" void kernel_launch(void* const* d_in, const int* in_sizes, int n_in,
                              void* d_out, int out_size)
{
    const float* query = (const float*)d_in[0];
    const float* key   = (const float*)d_in[1];
    const float* value = (const float*)d_in[2];
    const float* Wq    = (const float*)d_in[3];
    const float* bq    = (const float*)d_in[4];
    const float* Wk    = (const float*)d_in[5];
    const float* bk    = (const float*)d_in[6];
    const float* Wv    = (const float*)d_in[7];
    const float* bv    = (const float*)d_in[8];
    const float* wdel  = (const float*)d_in[9];
    const float* wsig  = (const float*)d_in[11];
    const float* wthe  = (const float*)d_in[13];
    float* out = (float*)d_out;

    const int PROJ_SMEM = PROJ_SMEM_FLOATS * (int)sizeof(float);   // 132608
    const int ATTN_SMEM = ATTN_SMEM_FLOATS * (int)sizeof(float);   // 150144

    cudaFuncSetAttribute(proj_kernel, cudaFuncAttributeMaxDynamicSharedMemorySize, PROJ_SMEM);
    cudaFuncSetAttribute(attn_kernel, cudaFuncAttributeMaxDynamicSharedMemorySize, ATTN_SMEM);

    proj_kernel<<<96, 256, PROJ_SMEM>>>(query, key, value, Wq, bq, Wk, bk, Wv, bv);
    attn_kernel<<<BB*16, 1024, ATTN_SMEM>>>(wdel, wsig, wthe, out);
}